// round 7
// baseline (speedup 1.0000x reference)
#include <cuda_runtime.h>
#include <cstdint>

#define NT 100
#define NBINS 101
#define THREADS 256
#define HIST_BYTES (NBINS * THREADS * 2)   // 51712, dynamic smem
#define BLOCKS 608                          // 152 SMs * 4 CTAs resident

// Global scratch (allocation-free). Zeroed at load; last block re-zeros after
// consuming -> deterministic across graph replays.
__device__ unsigned int g_hist_pos[NBINS];
__device__ unsigned int g_hist_all[NBINS];
__device__ unsigned int g_done;

__device__ __forceinline__ float thr_exact(int k) {
    return (float)((double)k * 0.01);
}
// cnt = ceil(p*100) (validated: ~1e-7 rel err vs exact searchsorted)
__device__ __forceinline__ int bin_of(float p) {
    int b = __float2int_ru(p * 100.0f);
    return min(max(b, 0), NT);
}

__device__ __forceinline__ void rmw4(unsigned short* __restrict__ my,
                                     float4 p, int4 g) {
    my[bin_of(p.x) * THREADS] += (unsigned short)(1u + ((unsigned)g.x << 8));
    my[bin_of(p.y) * THREADS] += (unsigned short)(1u + ((unsigned)g.y << 8));
    my[bin_of(p.z) * THREADS] += (unsigned short)(1u + ((unsigned)g.z << 8));
    my[bin_of(p.w) * THREADS] += (unsigned short)(1u + ((unsigned)g.w << 8));
}

__global__ void __launch_bounds__(THREADS, 4)
iou_kernel(const float* __restrict__ pred, const int* __restrict__ gt, int n,
           float* __restrict__ out, int out_size) {
    extern __shared__ unsigned char smem[];
    unsigned short* s_hist = (unsigned short*)smem;

    const int tid = threadIdx.x;

    // zero packed histogram
    {
        uint32_t* z = (uint32_t*)smem;
        #pragma unroll
        for (int i = tid; i < HIST_BYTES / 4; i += THREADS) z[i] = 0u;
    }
    __syncthreads();

    // Per-thread private u16 counter packed (all | pos<<8); halfword slot
    // 2*(tid&127)+(tid>>7) -> word index mod 32 == lane for every bin ->
    // provably conflict-free LDS/STS within each warp.
    const int slot = 2 * (tid & 127) + (tid >> 7);
    unsigned short* __restrict__ my = &s_hist[slot];

    const int n4 = n >> 2;
    const long long gtid = (long long)blockIdx.x * THREADS + tid;
    const long long stride = (long long)gridDim.x * THREADS;

    const float4* __restrict__ p4 = (const float4*)pred;
    const int4* __restrict__ g4 = (const int4*)gt;

    // Main loop: 3 independent coalesced streams; 6 LDG.128 issued
    // back-to-back per iteration (MLP_p1 = 6) before any consumption.
    long long i = gtid;
    for (; i + 2 * stride < n4; i += 3 * stride) {
        float4 pa = __ldcs(&p4[i]);
        float4 pb = __ldcs(&p4[i + stride]);
        float4 pc = __ldcs(&p4[i + 2 * stride]);
        int4 ga = __ldcs(&g4[i]);
        int4 gb = __ldcs(&g4[i + stride]);
        int4 gc = __ldcs(&g4[i + 2 * stride]);

        rmw4(my, pa, ga);
        rmw4(my, pb, gb);
        rmw4(my, pc, gc);
    }
    // leftover float4 steps
    for (; i < n4; i += stride) {
        float4 p = __ldcs(&p4[i]);
        int4 g = __ldcs(&g4[i]);
        rmw4(my, p, g);
    }
    // scalar remainder (none when n % 4 == 0)
    for (long long k = (long long)n4 * 4 + gtid; k < n; k += stride) {
        my[bin_of(pred[k]) * THREADS] +=
            (unsigned short)(1u + ((unsigned)(gt[k] != 0) << 8));
    }

    __syncthreads();

    // Block flush: warp w reduces bins {w, w+8, ...} via u32 reads of packed
    // u16 pairs (conflict-free strided), REDUX, 2 global atomics per bin.
    const int wid = tid >> 5;
    const int lane = tid & 31;
    const unsigned int* s32 = (const unsigned int*)s_hist;
    for (int b = wid; b < NBINS; b += (THREADS / 32)) {
        unsigned int acc_a = 0, acc_p = 0;
        #pragma unroll
        for (int k = 0; k < THREADS / 2 / 32; k++) {
            unsigned int v = s32[b * (THREADS / 2) + k * 32 + lane];
            acc_a += (v & 0xFFu) + ((v >> 16) & 0xFFu);
            acc_p += ((v >> 8) & 0xFFu) + (v >> 24);
        }
        unsigned int ra = __reduce_add_sync(0xFFFFFFFFu, acc_a);
        unsigned int rp = __reduce_add_sync(0xFFFFFFFFu, acc_p);
        if (lane == 0) {
            if (ra) atomicAdd(&g_hist_all[b], ra);
            if (rp) atomicAdd(&g_hist_pos[b], rp);
        }
    }

    // Last-block finalize (single launch total).
    __threadfence();
    __syncthreads();
    __shared__ unsigned int s_is_last;
    if (tid == 0) {
        unsigned int t = atomicAdd(&g_done, 1u);
        s_is_last = (t == gridDim.x - 1) ? 1u : 0u;
    }
    __syncthreads();
    if (!s_is_last) return;

    __shared__ unsigned int h_pos[NBINS];
    __shared__ unsigned int h_all[NBINS];
    if (tid < NBINS) {
        h_pos[tid] = g_hist_pos[tid];
        h_all[tid] = g_hist_all[tid];
        g_hist_pos[tid] = 0u;   // re-zero for next graph replay
        g_hist_all[tid] = 0u;
    }
    if (tid == 0) g_done = 0u;
    __syncthreads();

    if (tid < NT) {
        unsigned long long tp = 0, pp = 0, n_gt = 0;
        for (int c = tid + 1; c < NBINS; c++) {
            tp += h_pos[c];
            pp += h_all[c];
        }
        for (int c = 0; c < NBINS; c++) n_gt += h_pos[c];
        long long uni = (long long)pp + (long long)n_gt - (long long)tp;
        float iou = (uni > 0) ? ((float)((double)tp / (double)uni)) : 0.0f;

        if (out_size >= 2 * NT) {
            out[tid] = thr_exact(tid);
            out[NT + tid] = iou;
        } else {
            out[tid] = iou;
        }
    }
}

extern "C" void kernel_launch(void* const* d_in, const int* in_sizes, int n_in,
                              void* d_out, int out_size) {
    const float* pred = (const float*)d_in[0];
    const int* gt = (const int*)d_in[1];
    float* out = (float*)d_out;
    int n = in_sizes[0];

    cudaFuncSetAttribute(iou_kernel,
                         cudaFuncAttributeMaxDynamicSharedMemorySize,
                         HIST_BYTES);

    iou_kernel<<<BLOCKS, THREADS, HIST_BYTES>>>(pred, gt, n, out, out_size);
}

// round 8
// speedup vs baseline: 1.0058x; 1.0058x over previous
#include <cuda_runtime.h>
#include <cstdint>

#define NT 100
#define NBINS 101
#define THREADS 256
#define STAGES 6
#define TILE_EL 2048
#define PRED_TILE_BYTES (TILE_EL * 4)                 // 8192 (pred only via TMA)
#define HIST_BYTES (NBINS * THREADS * 2)              // 51712
#define STAGE_OFF(s) (HIST_BYTES + (s) * PRED_TILE_BYTES)
#define MBAR_OFF (HIST_BYTES + STAGES * PRED_TILE_BYTES)  // 100864
#define SMEM_TOTAL (MBAR_OFF + 64)
#define MIN_BLOCKS 608
#define MAX_TILES_PER_BLOCK 27         // 27*8 = 216 el/thread <= 255 (u8 safe)

// Global scratch (allocation-free). Zeroed at load; last block re-zeros after
// consuming -> deterministic across graph replays.
__device__ unsigned int g_hist_pos[NBINS];
__device__ unsigned int g_hist_all[NBINS];
__device__ unsigned int g_done;

__device__ __forceinline__ float thr_exact(int k) {
    return (float)((double)k * 0.01);
}
// cnt = ceil(p*100) (validated: ~1e-7 rel err vs exact searchsorted)
__device__ __forceinline__ int bin_of(float p) {
    int b = __float2int_ru(p * 100.0f);
    return min(max(b, 0), NT);
}

__device__ __forceinline__ void mbar_init(uint32_t mbar, uint32_t count) {
    asm volatile("mbarrier.init.shared.b64 [%0], %1;" :: "r"(mbar), "r"(count) : "memory");
}
__device__ __forceinline__ void mbar_expect_tx(uint32_t mbar, uint32_t bytes) {
    asm volatile("mbarrier.arrive.expect_tx.shared.b64 _, [%0], %1;"
                 :: "r"(mbar), "r"(bytes) : "memory");
}
__device__ __forceinline__ void mbar_wait(uint32_t mbar, uint32_t parity) {
    asm volatile(
        "{\n\t.reg .pred P;\n\t"
        "WAIT_%=:\n\t"
        "mbarrier.try_wait.parity.acquire.cta.shared::cta.b64 P, [%0], %1, 0x989680;\n\t"
        "@!P bra WAIT_%=;\n\t}"
        :: "r"(mbar), "r"(parity) : "memory");
}
__device__ __forceinline__ void bulk_g2s(uint32_t dst, const void* src,
                                         uint32_t bytes, uint32_t mbar) {
    asm volatile(
        "cp.async.bulk.shared::cta.global.mbarrier::complete_tx::bytes [%0], [%1], %2, [%3];"
        :: "r"(dst), "l"(src), "r"(bytes), "r"(mbar) : "memory");
}

__device__ __forceinline__ void rmw4(unsigned short* __restrict__ my,
                                     float4 p, int4 g) {
    my[bin_of(p.x) * THREADS] += (unsigned short)(1u + ((unsigned)g.x << 8));
    my[bin_of(p.y) * THREADS] += (unsigned short)(1u + ((unsigned)g.y << 8));
    my[bin_of(p.z) * THREADS] += (unsigned short)(1u + ((unsigned)g.z << 8));
    my[bin_of(p.w) * THREADS] += (unsigned short)(1u + ((unsigned)g.w << 8));
}

__global__ void __launch_bounds__(THREADS, 2)
iou_kernel(const float* __restrict__ pred, const int* __restrict__ gt, int n,
           float* __restrict__ out, int out_size) {
    extern __shared__ unsigned char smem[];
    unsigned short* s_hist = (unsigned short*)smem;

    const int tid = threadIdx.x;
    const uint32_t smem_base = (uint32_t)__cvta_generic_to_shared(smem);

    {
        uint32_t* z = (uint32_t*)smem;
        #pragma unroll
        for (int i = tid; i < HIST_BYTES / 4; i += THREADS) z[i] = 0u;
    }
    if (tid == 0) {
        #pragma unroll
        for (int s = 0; s < STAGES; s++) mbar_init(smem_base + MBAR_OFF + s * 8, 1u);
        asm volatile("fence.proxy.async.shared::cta;" ::: "memory");
    }
    __syncthreads();

    // Per-thread private u16 counter packed (all | pos<<8); halfword slot
    // 2*(tid&127)+(tid>>7) -> conflict-free LDS/STS within each warp.
    const int slot = 2 * (tid & 127) + (tid >> 7);
    unsigned short* __restrict__ my = &s_hist[slot];

    const int ntiles = n / TILE_EL;
    const int tpb = (ntiles + gridDim.x - 1) / gridDim.x;   // <= 27 by grid sizing
    const long long t0 = (long long)blockIdx.x * tpb;
    const int cnt = (t0 < ntiles)
                        ? (int)(((long long)ntiles - t0 < tpb) ? (ntiles - t0) : tpb)
                        : 0;

    const int4* __restrict__ g4 = (const int4*)gt;

    // prologue: producer fills up to STAGES stages with PRED tiles (TMA path)
    if (tid == 0) {
        int pro = (cnt < STAGES) ? cnt : STAGES;
        for (int k = 0; k < pro; k++) {
            uint32_t mbar = smem_base + MBAR_OFF + k * 8;
            mbar_expect_tx(mbar, PRED_TILE_BYTES);
            bulk_g2s(smem_base + STAGE_OFF(k), pred + (t0 + k) * TILE_EL,
                     PRED_TILE_BYTES, mbar);
        }
    }

    for (int k = 0; k < cnt; k++) {
        const int s = k % STAGES;
        const uint32_t mbar = smem_base + MBAR_OFF + s * 8;

        // gt via direct LDG.128 (separate injection path), issued BEFORE the
        // TMA wait so its latency hides behind the mbarrier spin.
        const long long gbase = (t0 + k) * (TILE_EL / 4) + tid;
        int4 ga = __ldcs(&g4[gbase]);
        int4 gb = __ldcs(&g4[gbase + THREADS]);

        mbar_wait(mbar, (uint32_t)((k / STAGES) & 1));

        const float4* __restrict__ sp = (const float4*)(smem + STAGE_OFF(s));
        float4 p0 = sp[tid];
        float4 p1 = sp[tid + THREADS];

        rmw4(my, p0, ga);
        rmw4(my, p1, gb);

        __syncthreads();   // all threads done reading stage s

        if (tid == 0 && (k + STAGES) < cnt) {
            mbar_expect_tx(mbar, PRED_TILE_BYTES);
            bulk_g2s(smem_base + STAGE_OFF(s), pred + (t0 + k + STAGES) * TILE_EL,
                     PRED_TILE_BYTES, mbar);
        }
    }

    // remainder beyond ntiles*TILE_EL (none for this n, kept for generality)
    const long long gtid = (long long)blockIdx.x * THREADS + tid;
    const long long stride = (long long)gridDim.x * THREADS;
    for (long long i = (long long)ntiles * TILE_EL + gtid; i < n; i += stride) {
        my[bin_of(pred[i]) * THREADS] +=
            (unsigned short)(1u + ((unsigned)(gt[i] != 0) << 8));
    }

    __syncthreads();

    // Block flush: warp w reduces bins {w, w+8, ...}: u32 reads of packed u16
    // pairs (conflict-free strided), REDUX, 2 global atomics per bin.
    const int wid = tid >> 5;
    const int lane = tid & 31;
    const unsigned int* s32 = (const unsigned int*)s_hist;
    for (int b = wid; b < NBINS; b += (THREADS / 32)) {
        unsigned int acc_a = 0, acc_p = 0;
        #pragma unroll
        for (int k = 0; k < THREADS / 2 / 32; k++) {
            unsigned int v = s32[b * (THREADS / 2) + k * 32 + lane];
            acc_a += (v & 0xFFu) + ((v >> 16) & 0xFFu);
            acc_p += ((v >> 8) & 0xFFu) + (v >> 24);
        }
        unsigned int ra = __reduce_add_sync(0xFFFFFFFFu, acc_a);
        unsigned int rp = __reduce_add_sync(0xFFFFFFFFu, acc_p);
        if (lane == 0) {
            if (ra) atomicAdd(&g_hist_all[b], ra);
            if (rp) atomicAdd(&g_hist_pos[b], rp);
        }
    }

    // Last-block finalize (single launch total).
    __threadfence();
    __syncthreads();
    __shared__ unsigned int s_is_last;
    if (tid == 0) {
        unsigned int t = atomicAdd(&g_done, 1u);
        s_is_last = (t == gridDim.x - 1) ? 1u : 0u;
    }
    __syncthreads();
    if (!s_is_last) return;

    __shared__ unsigned int h_pos[NBINS];
    __shared__ unsigned int h_all[NBINS];
    if (tid < NBINS) {
        h_pos[tid] = g_hist_pos[tid];
        h_all[tid] = g_hist_all[tid];
        g_hist_pos[tid] = 0u;
        g_hist_all[tid] = 0u;
    }
    if (tid == 0) g_done = 0u;
    __syncthreads();

    if (tid < NT) {
        unsigned long long tp = 0, pp = 0, n_gt = 0;
        for (int c = tid + 1; c < NBINS; c++) {
            tp += h_pos[c];
            pp += h_all[c];
        }
        for (int c = 0; c < NBINS; c++) n_gt += h_pos[c];
        long long uni = (long long)pp + (long long)n_gt - (long long)tp;
        float iou = (uni > 0) ? ((float)((double)tp / (double)uni)) : 0.0f;

        if (out_size >= 2 * NT) {
            out[tid] = thr_exact(tid);
            out[NT + tid] = iou;
        } else {
            out[tid] = iou;
        }
    }
}

extern "C" void kernel_launch(void* const* d_in, const int* in_sizes, int n_in,
                              void* d_out, int out_size) {
    const float* pred = (const float*)d_in[0];
    const int* gt = (const int*)d_in[1];
    float* out = (float*)d_out;
    int n = in_sizes[0];

    cudaFuncSetAttribute(iou_kernel,
                         cudaFuncAttributeMaxDynamicSharedMemorySize, SMEM_TOTAL);

    int ntiles = n / TILE_EL;
    long long need = ((long long)ntiles + MAX_TILES_PER_BLOCK - 1) /
                     MAX_TILES_PER_BLOCK;
    int blocks = (int)((need > MIN_BLOCKS) ? need : MIN_BLOCKS);

    iou_kernel<<<blocks, THREADS, SMEM_TOTAL>>>(pred, gt, n, out, out_size);
}

// round 9
// speedup vs baseline: 1.1801x; 1.1733x over previous
#include <cuda_runtime.h>
#include <cstdint>

#define NT 100
#define NBINS 101
#define THREADS 256
#define STAGES 6
#define TILE_EL 1024                           // elements per tile (4/thread)
#define PRED_STAGE_BYTES (TILE_EL * 4)         // 4096
#define GT_STAGE_BYTES (THREADS * 16)          // 4096 (16B per thread)
#define HIST_BYTES (NBINS * THREADS * 2)       // 51712
#define PRED_OFF(s) (HIST_BYTES + (s) * PRED_STAGE_BYTES)
#define GT_OFF(s) (HIST_BYTES + STAGES * PRED_STAGE_BYTES + (s) * GT_STAGE_BYTES)
#define MBAR_OFF (HIST_BYTES + STAGES * (PRED_STAGE_BYTES + GT_STAGE_BYTES))
#define SMEM_TOTAL (MBAR_OFF + 64)
#define MIN_BLOCKS 608
#define MAX_TILES_PER_BLOCK 54                 // 54*4 = 216 el/thread <= 255

// Global scratch (allocation-free). Zeroed at load; last block re-zeros after
// consuming -> deterministic across graph replays.
__device__ unsigned int g_hist_pos[NBINS];
__device__ unsigned int g_hist_all[NBINS];
__device__ unsigned int g_done;

__device__ __forceinline__ float thr_exact(int k) {
    return (float)((double)k * 0.01);
}
// cnt = ceil(p*100) (validated: ~1e-7 rel err vs exact searchsorted)
__device__ __forceinline__ int bin_of(float p) {
    int b = __float2int_ru(p * 100.0f);
    return min(max(b, 0), NT);
}

__device__ __forceinline__ void mbar_init(uint32_t mbar, uint32_t count) {
    asm volatile("mbarrier.init.shared.b64 [%0], %1;" :: "r"(mbar), "r"(count) : "memory");
}
__device__ __forceinline__ void mbar_expect_tx(uint32_t mbar, uint32_t bytes) {
    asm volatile("mbarrier.arrive.expect_tx.shared.b64 _, [%0], %1;"
                 :: "r"(mbar), "r"(bytes) : "memory");
}
__device__ __forceinline__ void mbar_wait(uint32_t mbar, uint32_t parity) {
    asm volatile(
        "{\n\t.reg .pred P;\n\t"
        "WAIT_%=:\n\t"
        "mbarrier.try_wait.parity.acquire.cta.shared::cta.b64 P, [%0], %1, 0x989680;\n\t"
        "@!P bra WAIT_%=;\n\t}"
        :: "r"(mbar), "r"(parity) : "memory");
}
__device__ __forceinline__ void bulk_g2s(uint32_t dst, const void* src,
                                         uint32_t bytes, uint32_t mbar) {
    asm volatile(
        "cp.async.bulk.shared::cta.global.mbarrier::complete_tx::bytes [%0], [%1], %2, [%3];"
        :: "r"(dst), "l"(src), "r"(bytes), "r"(mbar) : "memory");
}
__device__ __forceinline__ void cp16(uint32_t dst, const void* src) {
    asm volatile("cp.async.cg.shared.global [%0], [%1], 16;" :: "r"(dst), "l"(src));
}
__device__ __forceinline__ void cp_commit() {
    asm volatile("cp.async.commit_group;" ::: "memory");
}
template <int N>
__device__ __forceinline__ void cp_wait() {
    asm volatile("cp.async.wait_group %0;" :: "n"(N) : "memory");
}

__global__ void __launch_bounds__(THREADS, 2)
iou_kernel(const float* __restrict__ pred, const int* __restrict__ gt, int n,
           float* __restrict__ out, int out_size) {
    extern __shared__ unsigned char smem[];
    unsigned short* s_hist = (unsigned short*)smem;

    const int tid = threadIdx.x;
    const uint32_t smem_base = (uint32_t)__cvta_generic_to_shared(smem);

    {
        uint32_t* z = (uint32_t*)smem;
        #pragma unroll
        for (int i = tid; i < HIST_BYTES / 4; i += THREADS) z[i] = 0u;
    }
    if (tid == 0) {
        #pragma unroll
        for (int s = 0; s < STAGES; s++) mbar_init(smem_base + MBAR_OFF + s * 8, 1u);
        asm volatile("fence.proxy.async.shared::cta;" ::: "memory");
    }
    __syncthreads();

    // Per-thread private u16 counter packed (all | pos<<8); halfword slot
    // 2*(tid&127)+(tid>>7) -> conflict-free LDS/STS within each warp.
    const int slot = 2 * (tid & 127) + (tid >> 7);
    unsigned short* __restrict__ my = &s_hist[slot];

    const int ntiles = n / TILE_EL;
    const int tpb = (ntiles + gridDim.x - 1) / gridDim.x;   // <= 54 by grid sizing
    const long long t0 = (long long)blockIdx.x * tpb;
    const int cnt = (t0 < ntiles)
                        ? (int)(((long long)ntiles - t0 < tpb) ? (ntiles - t0) : tpb)
                        : 0;

    const int4* __restrict__ g4 = (const int4*)gt;
    const uint32_t gt_ring = smem_base + GT_OFF(0) + tid * 16;

    // prologue: fill both rings STAGES deep
    {
        int pro = (cnt < STAGES) ? cnt : STAGES;
        for (int k = 0; k < pro; k++) {
            if (tid == 0) {
                uint32_t mbar = smem_base + MBAR_OFF + k * 8;
                mbar_expect_tx(mbar, PRED_STAGE_BYTES);
                bulk_g2s(smem_base + PRED_OFF(k), pred + (t0 + k) * TILE_EL,
                         PRED_STAGE_BYTES, mbar);
            }
            cp16(gt_ring + (uint32_t)k * GT_STAGE_BYTES,
                 &g4[(t0 + k) * (TILE_EL / 4) + tid]);
            cp_commit();
        }
        for (int k = pro; k < STAGES; k++) cp_commit();  // stable group count
    }

    for (int k = 0; k < cnt; k++) {
        const int s = k % STAGES;

        // gt leg: keep the per-thread cp.async queue 6 deep, then retire
        // stage k's group. Independent of the TMA leg.
        {
            int kf = k + STAGES;
            if (kf < cnt) {
                cp16(gt_ring + (uint32_t)s * GT_STAGE_BYTES,
                     &g4[(t0 + kf) * (TILE_EL / 4) + tid]);
            }
            cp_commit();
            cp_wait<STAGES - 1>();
        }
        int4 g = *(const int4*)(smem + GT_OFF(s) + tid * 16);

        // pred leg: TMA stage k
        const uint32_t mbar = smem_base + MBAR_OFF + s * 8;
        mbar_wait(mbar, (uint32_t)((k / STAGES) & 1));
        float4 p = ((const float4*)(smem + PRED_OFF(s)))[tid];

        my[bin_of(p.x) * THREADS] += (unsigned short)(1u + ((unsigned)g.x << 8));
        my[bin_of(p.y) * THREADS] += (unsigned short)(1u + ((unsigned)g.y << 8));
        my[bin_of(p.z) * THREADS] += (unsigned short)(1u + ((unsigned)g.z << 8));
        my[bin_of(p.w) * THREADS] += (unsigned short)(1u + ((unsigned)g.w << 8));

        __syncthreads();   // all threads done with pred stage s

        if (tid == 0 && (k + STAGES) < cnt) {
            mbar_expect_tx(mbar, PRED_STAGE_BYTES);
            bulk_g2s(smem_base + PRED_OFF(s), pred + (t0 + k + STAGES) * TILE_EL,
                     PRED_STAGE_BYTES, mbar);
        }
    }
    cp_wait<0>();

    // remainder beyond ntiles*TILE_EL (none for this n, kept for generality)
    const long long gtid = (long long)blockIdx.x * THREADS + tid;
    const long long stride = (long long)gridDim.x * THREADS;
    for (long long i = (long long)ntiles * TILE_EL + gtid; i < n; i += stride) {
        my[bin_of(pred[i]) * THREADS] +=
            (unsigned short)(1u + ((unsigned)(gt[i] != 0) << 8));
    }

    __syncthreads();

    // Block flush: warp w reduces bins {w, w+8, ...}: u32 reads of packed u16
    // pairs (conflict-free strided), REDUX, 2 global atomics per bin.
    const int wid = tid >> 5;
    const int lane = tid & 31;
    const unsigned int* s32 = (const unsigned int*)s_hist;
    for (int b = wid; b < NBINS; b += (THREADS / 32)) {
        unsigned int acc_a = 0, acc_p = 0;
        #pragma unroll
        for (int kk = 0; kk < THREADS / 2 / 32; kk++) {
            unsigned int v = s32[b * (THREADS / 2) + kk * 32 + lane];
            acc_a += (v & 0xFFu) + ((v >> 16) & 0xFFu);
            acc_p += ((v >> 8) & 0xFFu) + (v >> 24);
        }
        unsigned int ra = __reduce_add_sync(0xFFFFFFFFu, acc_a);
        unsigned int rp = __reduce_add_sync(0xFFFFFFFFu, acc_p);
        if (lane == 0) {
            if (ra) atomicAdd(&g_hist_all[b], ra);
            if (rp) atomicAdd(&g_hist_pos[b], rp);
        }
    }

    // Last-block finalize (single launch total).
    __threadfence();
    __syncthreads();
    __shared__ unsigned int s_is_last;
    if (tid == 0) {
        unsigned int t = atomicAdd(&g_done, 1u);
        s_is_last = (t == gridDim.x - 1) ? 1u : 0u;
    }
    __syncthreads();
    if (!s_is_last) return;

    __shared__ unsigned int h_pos[NBINS];
    __shared__ unsigned int h_all[NBINS];
    if (tid < NBINS) {
        h_pos[tid] = g_hist_pos[tid];
        h_all[tid] = g_hist_all[tid];
        g_hist_pos[tid] = 0u;
        g_hist_all[tid] = 0u;
    }
    if (tid == 0) g_done = 0u;
    __syncthreads();

    if (tid < NT) {
        unsigned long long tp = 0, pp = 0, n_gt = 0;
        for (int c = tid + 1; c < NBINS; c++) {
            tp += h_pos[c];
            pp += h_all[c];
        }
        for (int c = 0; c < NBINS; c++) n_gt += h_pos[c];
        long long uni = (long long)pp + (long long)n_gt - (long long)tp;
        float iou = (uni > 0) ? ((float)((double)tp / (double)uni)) : 0.0f;

        if (out_size >= 2 * NT) {
            out[tid] = thr_exact(tid);
            out[NT + tid] = iou;
        } else {
            out[tid] = iou;
        }
    }
}

extern "C" void kernel_launch(void* const* d_in, const int* in_sizes, int n_in,
                              void* d_out, int out_size) {
    const float* pred = (const float*)d_in[0];
    const int* gt = (const int*)d_in[1];
    float* out = (float*)d_out;
    int n = in_sizes[0];

    cudaFuncSetAttribute(iou_kernel,
                         cudaFuncAttributeMaxDynamicSharedMemorySize, SMEM_TOTAL);

    int ntiles = n / TILE_EL;
    long long need = ((long long)ntiles + MAX_TILES_PER_BLOCK - 1) /
                     MAX_TILES_PER_BLOCK;
    int blocks = (int)((need > MIN_BLOCKS) ? need : MIN_BLOCKS);

    iou_kernel<<<blocks, THREADS, SMEM_TOTAL>>>(pred, gt, n, out, out_size);
}